// round 7
// baseline (speedup 1.0000x reference)
// LogEntmaxBisect — log(entmax_1.5(X)) for X[4096, 32000] fp32.
//
// R7: persistent work-stealing CTAs + cross-row software pipeline.
// Each CTA steals rows from a global counter. The merged loop for row r
// streams row r from DRAM (stats: max/min/S1/S2) while re-reading row r-1
// from L2 (__ldcs, last use) and streaming out log p (__stcs). The only
// per-row serialization left is the block reduce + fp64 closed-form tau/Z
// solve (~1us), hidden by 4 CTAs/SM. No wave transitions.
// Generic quadratic-refine fallback (never taken on dense-support data).

#include <cuda_runtime.h>
#include <math.h>

#define D_DIM   32000
#define NT      384
#define NVROW   (D_DIM / 4)       // 8000 float4 per row
#define NITER   21                // ceil(8000 / 384)
#define NWARP   (NT / 32)         // 12
#define GRID    592               // 148 SMs x 4 CTAs (work-stealing tolerates fewer resident)
#define TAU_GAP 0.005590169943749474   // (1/d)^(alpha-1) = 1/sqrt(32000)
#define TWO_LN2 1.3862943611198906f

__device__ unsigned g_row_ctr;

__global__ void init_ctr_kernel() { g_row_ctr = 0u; }

__global__ void __launch_bounds__(NT, 4)
log_entmax_kernel(const float* __restrict__ X, float* __restrict__ Y, int nrows)
{
    const int tid  = threadIdx.x;
    const int lane = tid & 31;
    const int wid  = tid >> 5;          // 0..11

    __shared__ float sred[4 * NWARP];
    __shared__ float sbc[3];            // [0]=tau [1]=-log(Z) or sentinel [2]=tau_hi
    __shared__ unsigned srow;

    int   prev = -1;                    // previous row (output pending)
    float tau  = 0.0f, nlZ = 0.0f;      // its solved threshold / -log(Z)

    for (;;) {
        if (tid == 0) srow = atomicAdd(&g_row_ctr, 1u);
        __syncthreads();                // also fences sred/sbc reuse across rows
        const int r = (int)srow;
        if (r >= nrows) break;

        const float4* __restrict__ Xn = (const float4*)(X + (size_t)r * D_DIM);

        // ---- stats for row r, merged with output of row prev ----------
        float M = -3.0e38f, mn = 3.0e38f, S1 = 0.0f, S2 = 0.0f;
        if (prev < 0) {
            #pragma unroll 4
            for (int j = 0; j < NITER; j++) {
                const int i4 = tid + j * NT;
                if (i4 < NVROW) {
                    const float4 v = Xn[i4];
                    M  = fmaxf(M,  fmaxf(fmaxf(v.x, v.y), fmaxf(v.z, v.w)));
                    mn = fminf(mn, fminf(fminf(v.x, v.y), fminf(v.z, v.w)));
                    S1 += ((v.x + v.y) + (v.z + v.w));
                    S2 = fmaf(v.x, v.x, S2); S2 = fmaf(v.y, v.y, S2);
                    S2 = fmaf(v.z, v.z, S2); S2 = fmaf(v.w, v.w, S2);
                }
            }
        } else {
            const float4* __restrict__ Xp = (const float4*)(X + (size_t)prev * D_DIM);
            float4*       __restrict__ Yp = (float4*)(Y + (size_t)prev * D_DIM);
            #pragma unroll 2
            for (int j = 0; j < NITER; j++) {
                const int i4 = tid + j * NT;
                if (i4 < NVROW) {
                    const float4 v = Xn[i4];              // DRAM stream (row r)
                    M  = fmaxf(M,  fmaxf(fmaxf(v.x, v.y), fmaxf(v.z, v.w)));
                    mn = fminf(mn, fminf(fminf(v.x, v.y), fminf(v.z, v.w)));
                    S1 += ((v.x + v.y) + (v.z + v.w));
                    S2 = fmaf(v.x, v.x, S2); S2 = fmaf(v.y, v.y, S2);
                    S2 = fmaf(v.z, v.z, S2); S2 = fmaf(v.w, v.w, S2);
                    const float4 u = __ldcs(&Xp[i4]);     // L2-hot, last use
                    float4 o;
                    o.x = fmaf(TWO_LN2, __log2f(fmaxf(fmaf(u.x, 0.5f, -tau), 0.0f)), nlZ);
                    o.y = fmaf(TWO_LN2, __log2f(fmaxf(fmaf(u.y, 0.5f, -tau), 0.0f)), nlZ);
                    o.z = fmaf(TWO_LN2, __log2f(fmaxf(fmaf(u.z, 0.5f, -tau), 0.0f)), nlZ);
                    o.w = fmaf(TWO_LN2, __log2f(fmaxf(fmaf(u.w, 0.5f, -tau), 0.0f)), nlZ);
                    __stcs(&Yp[i4], o);                   // streaming store
                }
            }
        }

        // ---- block reduction of {max, min, S1, S2} ---------------------
        #pragma unroll
        for (int o = 16; o > 0; o >>= 1) {
            M  = fmaxf(M,  __shfl_xor_sync(0xffffffffu, M,  o));
            mn = fminf(mn, __shfl_xor_sync(0xffffffffu, mn, o));
            S1 += __shfl_xor_sync(0xffffffffu, S1, o);
            S2 += __shfl_xor_sync(0xffffffffu, S2, o);
        }
        if (lane == 0) {
            sred[wid] = M; sred[NWARP + wid] = mn;
            sred[2 * NWARP + wid] = S1; sred[3 * NWARP + wid] = S2;
        }
        __syncthreads();
        if (wid == 0) {
            float m = (lane < NWARP) ? sred[lane]             : -3.0e38f;
            float n = (lane < NWARP) ? sred[NWARP + lane]     :  3.0e38f;
            float a = (lane < NWARP) ? sred[2 * NWARP + lane] :  0.0f;
            float b = (lane < NWARP) ? sred[3 * NWARP + lane] :  0.0f;
            #pragma unroll
            for (int o = 8; o > 0; o >>= 1) {
                m = fmaxf(m, __shfl_xor_sync(0xffffffffu, m, o));
                n = fminf(n, __shfl_xor_sync(0xffffffffu, n, o));
                a += __shfl_xor_sync(0xffffffffu, a, o);
                b += __shfl_xor_sync(0xffffffffu, b, o);
            }
            if (lane == 0) {
                // fp64 scalar solve (shifted to Xs = 0.5*X frame)
                const double d   = (double)D_DIM;
                const double mu  = 0.5 * (double)a / d;
                const double S2q = 0.25 * (double)b;
                const double V   = S2q - d * mu * mu;        // Sum (Xs - mu)^2
                const double m2  = 0.5 * (double)m;
                const double thi = m2 - TAU_GAP;             // tau_hi
                const double arg = (1.0 - V) / d;
                double t = (arg > 0.0) ? (mu - sqrt(arg)) : (m2 - 1.0);
                if (t > thi)      t = thi;
                if (t < m2 - 1.0) t = m2 - 1.0;
                const float tauf = (float)t;
                const bool dense = (arg > 0.0) && (0.5 * (double)n > (double)tauf);
                const double dmu = mu - (double)tauf;
                const double Z   = V + d * dmu * dmu;
                sbc[0] = tauf;
                sbc[1] = dense ? (float)(-log(Z)) : 1.0e30f;  // sentinel -> refine
                sbc[2] = (float)thi;
            }
        }
        __syncthreads();
        tau = sbc[0];
        nlZ = sbc[1];

        // ---- Fallback: one generic active-set quadratic refinement -----
        if (nlZ > 1.0e29f) {                   // uniform across block
            __syncthreads();
            float C = 0.0f, F1 = 0.0f, F2 = 0.0f;
            #pragma unroll 4
            for (int j = 0; j < NITER; j++) {
                const int i4 = tid + j * NT;
                if (i4 < NVROW) {
                    const float4 v = Xn[i4];   // L2-hot (just streamed)
                    #pragma unroll
                    for (int q = 0; q < 4; q++) {
                        const float xv = (q == 0) ? v.x : (q == 1) ? v.y : (q == 2) ? v.z : v.w;
                        const float t = fmaf(xv, 0.5f, -tau);
                        const float rr = fmaxf(t, 0.0f);
                        if (t > 0.0f) C += 1.0f;
                        F1 += rr;
                        F2 = fmaf(rr, rr, F2);
                    }
                }
            }
            #pragma unroll
            for (int o = 16; o > 0; o >>= 1) {
                C  += __shfl_xor_sync(0xffffffffu, C,  o);
                F1 += __shfl_xor_sync(0xffffffffu, F1, o);
                F2 += __shfl_xor_sync(0xffffffffu, F2, o);
            }
            if (lane == 0) { sred[wid] = C; sred[NWARP + wid] = F1; sred[2 * NWARP + wid] = F2; }
            __syncthreads();
            if (wid == 0) {
                float c  = (lane < NWARP) ? sred[lane]             : 0.0f;
                float f1 = (lane < NWARP) ? sred[NWARP + lane]     : 0.0f;
                float f2 = (lane < NWARP) ? sred[2 * NWARP + lane] : 0.0f;
                #pragma unroll
                for (int o = 8; o > 0; o >>= 1) {
                    c  += __shfl_xor_sync(0xffffffffu, c,  o);
                    f1 += __shfl_xor_sync(0xffffffffu, f1, o);
                    f2 += __shfl_xor_sync(0xffffffffu, f2, o);
                }
                if (lane == 0) {
                    float disc = fmaxf(fmaf(-c, f2 - 1.0f, f1 * f1), 0.0f);
                    const float delta = (f1 - sqrtf(disc)) / c;
                    const float tn = fminf(tau + delta, sbc[2]);
                    const float dd = tn - tau;
                    const float Zr = fmaf(c, dd * dd, fmaf(-2.0f * f1, dd, f2));
                    sbc[0] = tn;
                    sbc[1] = -__logf(fmaxf(Zr, 1.0e-30f));
                }
            }
            __syncthreads();
            tau = sbc[0];
            nlZ = sbc[1];
        }

        prev = r;
    }

    // ---- Epilogue: output the last stolen row --------------------------
    if (prev >= 0) {
        const float4* __restrict__ Xp = (const float4*)(X + (size_t)prev * D_DIM);
        float4*       __restrict__ Yp = (float4*)(Y + (size_t)prev * D_DIM);
        #pragma unroll 4
        for (int j = 0; j < NITER; j++) {
            const int i4 = tid + j * NT;
            if (i4 < NVROW) {
                const float4 u = __ldcs(&Xp[i4]);
                float4 o;
                o.x = fmaf(TWO_LN2, __log2f(fmaxf(fmaf(u.x, 0.5f, -tau), 0.0f)), nlZ);
                o.y = fmaf(TWO_LN2, __log2f(fmaxf(fmaf(u.y, 0.5f, -tau), 0.0f)), nlZ);
                o.z = fmaf(TWO_LN2, __log2f(fmaxf(fmaf(u.z, 0.5f, -tau), 0.0f)), nlZ);
                o.w = fmaf(TWO_LN2, __log2f(fmaxf(fmaf(u.w, 0.5f, -tau), 0.0f)), nlZ);
                __stcs(&Yp[i4], o);
            }
        }
    }
}

extern "C" void kernel_launch(void* const* d_in, const int* in_sizes, int n_in,
                              void* d_out, int out_size)
{
    const float* X = (const float*)d_in[0];
    float*       Y = (float*)d_out;
    const int rows = in_sizes[0] / D_DIM;     // 4096
    init_ctr_kernel<<<1, 1>>>();
    log_entmax_kernel<<<GRID, NT>>>(X, Y, rows);
}

// round 8
// speedup vs baseline: 1.2580x; 1.2580x over previous
// LogEntmaxBisect — log(entmax_1.5(X)) for X[4096, 32000] fp32.
//
// R8 = R6 structure + persistent work-stealing (no cross-row pipeline!).
// R7 lesson: overlapping row r's stream with row r-1's re-read keeps 2 rows
// live per CTA -> 151MB L2 footprint -> re-reads miss to DRAM (+330MB).
// Here each stolen row runs the proven two-pass scheme: pass 1 streams via
// 256-bit L2::evict_last loads ({max,min,S1,S2}), fp64 closed-form tau/Z,
// pass 2 re-reads L2-hot via __ldcs and streams out via __stcs. Persistence
// removes the 6.9 synchronized launch waves whose transitions dipped DRAM
// demand in R6. Footprint: 1 row/CTA x 592 = 76MB < 126MB L2.

#include <cuda_runtime.h>
#include <math.h>

#define D_DIM   32000
#define NT      384
#define NVROW   (D_DIM / 4)       // 8000 float4 per row
#define NROW8   (D_DIM / 8)       // 4000 float8 per row
#define NITER   21                // ceil(8000 / 384)
#define NIT8    11                // ceil(4000 / 384)
#define NWARP   (NT / 32)         // 12
#define GRID    592               // 148 SMs x 4 CTAs
#define TAU_GAP 0.005590169943749474   // (1/d)^(alpha-1) = 1/sqrt(32000)
#define TWO_LN2 1.3862943611198906f

__device__ unsigned g_row_ctr;

__global__ void init_ctr_kernel() { g_row_ctr = 0u; }

// 256-bit load with L2 evict_last (keep for this CTA's pass-2 reuse)
__device__ __forceinline__ void ldg256_keep(const float* p, float* v)
{
    unsigned r0, r1, r2, r3, r4, r5, r6, r7;
    asm("ld.global.L2::evict_last.v8.b32 {%0,%1,%2,%3,%4,%5,%6,%7}, [%8];"
        : "=r"(r0), "=r"(r1), "=r"(r2), "=r"(r3),
          "=r"(r4), "=r"(r5), "=r"(r6), "=r"(r7) : "l"(p));
    v[0] = __uint_as_float(r0); v[1] = __uint_as_float(r1);
    v[2] = __uint_as_float(r2); v[3] = __uint_as_float(r3);
    v[4] = __uint_as_float(r4); v[5] = __uint_as_float(r5);
    v[6] = __uint_as_float(r6); v[7] = __uint_as_float(r7);
}

__global__ void __launch_bounds__(NT, 4)
log_entmax_kernel(const float* __restrict__ X, float* __restrict__ Y, int nrows)
{
    const int tid  = threadIdx.x;
    const int lane = tid & 31;
    const int wid  = tid >> 5;          // 0..11

    __shared__ float sred[4 * NWARP];
    __shared__ float sbc[3];            // [0]=tau [1]=-log(Z) or sentinel [2]=tau_hi
    __shared__ unsigned srow;

    for (;;) {
        if (tid == 0) srow = atomicAdd(&g_row_ctr, 1u);
        __syncthreads();                // fences sred/sbc reuse across rows too
        const int r = (int)srow;
        if (r >= nrows) break;

        const float*  __restrict__ Xs = X + (size_t)r * D_DIM;
        const float4* __restrict__ Xr = (const float4*)Xs;
        float4*       __restrict__ Yr = (float4*)(Y + (size_t)r * D_DIM);

        // ---- Pass 1: stream row via 32B evict_last loads ----------------
        float M = -3.0e38f, mn = 3.0e38f, S1 = 0.0f, S2 = 0.0f;
        #pragma unroll
        for (int j = 0; j < NIT8; j++) {
            const int i8 = tid + j * NT;
            if (i8 < NROW8) {
                float v[8];
                ldg256_keep(Xs + i8 * 8, v);
                #pragma unroll
                for (int q = 0; q < 8; q++) {
                    M  = fmaxf(M,  v[q]);
                    mn = fminf(mn, v[q]);
                    S1 += v[q];
                    S2 = fmaf(v[q], v[q], S2);
                }
            }
        }

        // ---- block reduction of {max, min, S1, S2} ----------------------
        #pragma unroll
        for (int o = 16; o > 0; o >>= 1) {
            M  = fmaxf(M,  __shfl_xor_sync(0xffffffffu, M,  o));
            mn = fminf(mn, __shfl_xor_sync(0xffffffffu, mn, o));
            S1 += __shfl_xor_sync(0xffffffffu, S1, o);
            S2 += __shfl_xor_sync(0xffffffffu, S2, o);
        }
        if (lane == 0) {
            sred[wid] = M; sred[NWARP + wid] = mn;
            sred[2 * NWARP + wid] = S1; sred[3 * NWARP + wid] = S2;
        }
        __syncthreads();
        if (wid == 0) {
            float m = (lane < NWARP) ? sred[lane]             : -3.0e38f;
            float n = (lane < NWARP) ? sred[NWARP + lane]     :  3.0e38f;
            float a = (lane < NWARP) ? sred[2 * NWARP + lane] :  0.0f;
            float b = (lane < NWARP) ? sred[3 * NWARP + lane] :  0.0f;
            #pragma unroll
            for (int o = 8; o > 0; o >>= 1) {
                m = fmaxf(m, __shfl_xor_sync(0xffffffffu, m, o));
                n = fminf(n, __shfl_xor_sync(0xffffffffu, n, o));
                a += __shfl_xor_sync(0xffffffffu, a, o);
                b += __shfl_xor_sync(0xffffffffu, b, o);
            }
            if (lane == 0) {
                // fp64 scalar solve (shifted to Xs = 0.5*X frame)
                const double d   = (double)D_DIM;
                const double mu  = 0.5 * (double)a / d;
                const double S2q = 0.25 * (double)b;
                const double V   = S2q - d * mu * mu;        // Sum (Xs - mu)^2
                const double m2  = 0.5 * (double)m;
                const double thi = m2 - TAU_GAP;             // tau_hi
                const double arg = (1.0 - V) / d;
                double t = (arg > 0.0) ? (mu - sqrt(arg)) : (m2 - 1.0);
                if (t > thi)      t = thi;
                if (t < m2 - 1.0) t = m2 - 1.0;
                const float tauf = (float)t;
                // dense support <=> min element still active at tau
                const bool dense = (arg > 0.0) && (0.5 * (double)n > (double)tauf);
                // Z = Sum r^2 at the fp32-rounded tau (exact under dense support)
                const double dmu = mu - (double)tauf;
                const double Z   = V + d * dmu * dmu;
                sbc[0] = tauf;
                sbc[1] = dense ? (float)(-log(Z)) : 1.0e30f;  // sentinel -> refine
                sbc[2] = (float)thi;
            }
        }
        __syncthreads();
        float tau = sbc[0];
        float nlZ = sbc[1];

        // ---- Fallback: one generic active-set quadratic refinement ------
        // (re-reads the L2-hot row; never taken on dense-support data)
        if (nlZ > 1.0e29f) {                   // uniform across block
            __syncthreads();
            float C = 0.0f, F1 = 0.0f, F2 = 0.0f;
            #pragma unroll 4
            for (int j = 0; j < NITER; j++) {
                const int i4 = tid + j * NT;
                if (i4 < NVROW) {
                    const float4 v = Xr[i4];
                    #pragma unroll
                    for (int q = 0; q < 4; q++) {
                        const float xv = (q == 0) ? v.x : (q == 1) ? v.y : (q == 2) ? v.z : v.w;
                        const float t = fmaf(xv, 0.5f, -tau);
                        const float rr = fmaxf(t, 0.0f);
                        if (t > 0.0f) C += 1.0f;
                        F1 += rr;
                        F2 = fmaf(rr, rr, F2);
                    }
                }
            }
            #pragma unroll
            for (int o = 16; o > 0; o >>= 1) {
                C  += __shfl_xor_sync(0xffffffffu, C,  o);
                F1 += __shfl_xor_sync(0xffffffffu, F1, o);
                F2 += __shfl_xor_sync(0xffffffffu, F2, o);
            }
            if (lane == 0) { sred[wid] = C; sred[NWARP + wid] = F1; sred[2 * NWARP + wid] = F2; }
            __syncthreads();
            if (wid == 0) {
                float c  = (lane < NWARP) ? sred[lane]             : 0.0f;
                float f1 = (lane < NWARP) ? sred[NWARP + lane]     : 0.0f;
                float f2 = (lane < NWARP) ? sred[2 * NWARP + lane] : 0.0f;
                #pragma unroll
                for (int o = 8; o > 0; o >>= 1) {
                    c  += __shfl_xor_sync(0xffffffffu, c,  o);
                    f1 += __shfl_xor_sync(0xffffffffu, f1, o);
                    f2 += __shfl_xor_sync(0xffffffffu, f2, o);
                }
                if (lane == 0) {
                    float disc = fmaxf(fmaf(-c, f2 - 1.0f, f1 * f1), 0.0f);
                    const float delta = (f1 - sqrtf(disc)) / c;
                    const float tn = fminf(tau + delta, sbc[2]);
                    const float dd = tn - tau;
                    const float Zr = fmaf(c, dd * dd, fmaf(-2.0f * f1, dd, f2));
                    sbc[0] = tn;
                    sbc[1] = -__logf(fmaxf(Zr, 1.0e-30f));
                }
            }
            __syncthreads();
            tau = sbc[0];
            nlZ = sbc[1];
        }

        // ---- Pass 2: re-read row (L2-hot, last-use), stream output ------
        #pragma unroll 4
        for (int j = 0; j < NITER; j++) {
            const int i4 = tid + j * NT;
            if (i4 < NVROW) {
                const float4 v = __ldcs(&Xr[i4]);     // evict-first: last use
                float4 o;
                o.x = fmaf(TWO_LN2, __log2f(fmaxf(fmaf(v.x, 0.5f, -tau), 0.0f)), nlZ);
                o.y = fmaf(TWO_LN2, __log2f(fmaxf(fmaf(v.y, 0.5f, -tau), 0.0f)), nlZ);
                o.z = fmaf(TWO_LN2, __log2f(fmaxf(fmaf(v.z, 0.5f, -tau), 0.0f)), nlZ);
                o.w = fmaf(TWO_LN2, __log2f(fmaxf(fmaf(v.w, 0.5f, -tau), 0.0f)), nlZ);
                __stcs(&Yr[i4], o);                   // streaming store
            }
        }
        // no extra sync needed: next iteration's __syncthreads() covers reuse
    }
}

extern "C" void kernel_launch(void* const* d_in, const int* in_sizes, int n_in,
                              void* d_out, int out_size)
{
    const float* X = (const float*)d_in[0];
    float*       Y = (float*)d_out;
    const int rows = in_sizes[0] / D_DIM;     // 4096
    init_ctr_kernel<<<1, 1>>>();
    log_entmax_kernel<<<GRID, NT>>>(X, Y, rows);
}

// round 9
// speedup vs baseline: 1.3485x; 1.0719x over previous
// LogEntmaxBisect — log(entmax_1.5(X)) for X[4096, 32000] fp32.
//
// R9 = R6 (best: plain grid, evict_last 256b pass-1 loads, ldcs/stcs pass 2)
// with a cheap solve: the one-thread per-row solve previously called
// double sqrt() and double log() (software routines, ~1-3k cyc) while the
// whole CTA waited at the barrier — and CTAs on an SM run in phase, so the
// bubbles aligned and drained DRAM demand. Replaced with fp32 sqrtf/__logf
// (error contribution ~1e-9 abs on tau, ~1e-8 on log Z — negligible);
// fp64 kept only for the cheap DFMA accumulation of mu/V/Z.

#include <cuda_runtime.h>
#include <math.h>

#define D_DIM   32000
#define NT      384
#define NVROW   (D_DIM / 4)       // 8000 float4 per row
#define NROW8   (D_DIM / 8)       // 4000 float8 per row
#define NITER   21                // ceil(8000 / 384)
#define NIT8    11                // ceil(4000 / 384)
#define NWARP   (NT / 32)         // 12
#define TAU_GAP 0.005590169943749474   // (1/d)^(alpha-1) = 1/sqrt(32000)
#define TWO_LN2 1.3862943611198906f

// 256-bit load with L2 evict_last (keep for this CTA's pass-2 reuse)
__device__ __forceinline__ void ldg256_keep(const float* p, float* v)
{
    unsigned r0, r1, r2, r3, r4, r5, r6, r7;
    asm("ld.global.L2::evict_last.v8.b32 {%0,%1,%2,%3,%4,%5,%6,%7}, [%8];"
        : "=r"(r0), "=r"(r1), "=r"(r2), "=r"(r3),
          "=r"(r4), "=r"(r5), "=r"(r6), "=r"(r7) : "l"(p));
    v[0] = __uint_as_float(r0); v[1] = __uint_as_float(r1);
    v[2] = __uint_as_float(r2); v[3] = __uint_as_float(r3);
    v[4] = __uint_as_float(r4); v[5] = __uint_as_float(r5);
    v[6] = __uint_as_float(r6); v[7] = __uint_as_float(r7);
}

__global__ void __launch_bounds__(NT, 4)
log_entmax_kernel(const float* __restrict__ X, float* __restrict__ Y)
{
    const int tid  = threadIdx.x;
    const int lane = tid & 31;
    const int wid  = tid >> 5;          // 0..11

    __shared__ float sred[4 * NWARP];
    __shared__ float sbc[3];            // [0]=tau [1]=-log(Z) or sentinel [2]=tau_hi

    const size_t base = (size_t)blockIdx.x * D_DIM;
    const float*  __restrict__ Xs = X + base;
    const float4* __restrict__ Xr = (const float4*)Xs;
    float4*       __restrict__ Yr = (float4*)(Y + base);

    // ---- Pass 1: stream row via 32B evict_last loads, {max,min,S1,S2} --
    float M = -3.0e38f, mn = 3.0e38f, S1 = 0.0f, S2 = 0.0f;
    #pragma unroll
    for (int j = 0; j < NIT8; j++) {
        const int i8 = tid + j * NT;
        if (i8 < NROW8) {
            float v[8];
            ldg256_keep(Xs + i8 * 8, v);
            #pragma unroll
            for (int q = 0; q < 8; q++) {
                M  = fmaxf(M,  v[q]);
                mn = fminf(mn, v[q]);
                S1 += v[q];
                S2 = fmaf(v[q], v[q], S2);
            }
        }
    }

    // ---- Single block reduction of 4 values ----------------------------
    #pragma unroll
    for (int o = 16; o > 0; o >>= 1) {
        M  = fmaxf(M,  __shfl_xor_sync(0xffffffffu, M,  o));
        mn = fminf(mn, __shfl_xor_sync(0xffffffffu, mn, o));
        S1 += __shfl_xor_sync(0xffffffffu, S1, o);
        S2 += __shfl_xor_sync(0xffffffffu, S2, o);
    }
    if (lane == 0) {
        sred[wid] = M; sred[NWARP + wid] = mn;
        sred[2 * NWARP + wid] = S1; sred[3 * NWARP + wid] = S2;
    }
    __syncthreads();
    if (wid == 0) {
        float m = (lane < NWARP) ? sred[lane]             : -3.0e38f;
        float n = (lane < NWARP) ? sred[NWARP + lane]     :  3.0e38f;
        float a = (lane < NWARP) ? sred[2 * NWARP + lane] :  0.0f;
        float b = (lane < NWARP) ? sred[3 * NWARP + lane] :  0.0f;
        #pragma unroll
        for (int o = 8; o > 0; o >>= 1) {
            m = fmaxf(m, __shfl_xor_sync(0xffffffffu, m, o));
            n = fminf(n, __shfl_xor_sync(0xffffffffu, n, o));
            a += __shfl_xor_sync(0xffffffffu, a, o);
            b += __shfl_xor_sync(0xffffffffu, b, o);
        }
        if (lane == 0) {
            // Scalar solve: fp64 accumulation, fp32 sqrt/log (cheap MUFU path)
            const double d   = (double)D_DIM;
            const double mu  = 0.5 * (double)a / d;
            const double S2q = 0.25 * (double)b;
            const double V   = S2q - d * mu * mu;        // Sum (Xs - mu)^2
            const double m2  = 0.5 * (double)m;
            const double thi = m2 - TAU_GAP;             // tau_hi
            const double arg = (1.0 - V) / d;
            // fp32 sqrt: rel err ~1e-7 on sqrt(arg)~5.6e-3 -> tau abs ~6e-10
            double t = (arg > 0.0) ? (mu - (double)sqrtf((float)arg)) : (m2 - 1.0);
            if (t > thi)      t = thi;
            if (t < m2 - 1.0) t = m2 - 1.0;
            const float tauf = (float)t;
            // dense support <=> min element still active at tau
            const bool dense = (arg > 0.0) && (0.5 * (double)n > (double)tauf);
            // Z = Sum r^2 at the fp32-rounded tau (exact under dense support)
            const double dmu = mu - (double)tauf;
            const double Z   = V + d * dmu * dmu;        // ~1 by construction
            sbc[0] = tauf;
            sbc[1] = dense ? (-__logf((float)Z)) : 1.0e30f;  // sentinel -> refine
            sbc[2] = (float)thi;
        }
    }
    __syncthreads();
    float tau = sbc[0];
    float nlZ = sbc[1];

    // ---- Fallback: one generic active-set quadratic refinement ---------
    // (re-reads the L2-hot row; never taken on dense-support data)
    if (nlZ > 1.0e29f) {                   // uniform across block
        __syncthreads();                   // protect sred/sbc reuse
        float C = 0.0f, F1 = 0.0f, F2 = 0.0f;
        #pragma unroll 4
        for (int j = 0; j < NITER; j++) {
            const int i4 = tid + j * NT;
            if (i4 < NVROW) {
                const float4 v = Xr[i4];
                #pragma unroll
                for (int q = 0; q < 4; q++) {
                    const float xv = (q == 0) ? v.x : (q == 1) ? v.y : (q == 2) ? v.z : v.w;
                    const float t = fmaf(xv, 0.5f, -tau);
                    const float rr = fmaxf(t, 0.0f);
                    if (t > 0.0f) C += 1.0f;
                    F1 += rr;
                    F2 = fmaf(rr, rr, F2);
                }
            }
        }
        #pragma unroll
        for (int o = 16; o > 0; o >>= 1) {
            C  += __shfl_xor_sync(0xffffffffu, C,  o);
            F1 += __shfl_xor_sync(0xffffffffu, F1, o);
            F2 += __shfl_xor_sync(0xffffffffu, F2, o);
        }
        if (lane == 0) { sred[wid] = C; sred[NWARP + wid] = F1; sred[2 * NWARP + wid] = F2; }
        __syncthreads();
        if (wid == 0) {
            float c  = (lane < NWARP) ? sred[lane]             : 0.0f;
            float f1 = (lane < NWARP) ? sred[NWARP + lane]     : 0.0f;
            float f2 = (lane < NWARP) ? sred[2 * NWARP + lane] : 0.0f;
            #pragma unroll
            for (int o = 8; o > 0; o >>= 1) {
                c  += __shfl_xor_sync(0xffffffffu, c,  o);
                f1 += __shfl_xor_sync(0xffffffffu, f1, o);
                f2 += __shfl_xor_sync(0xffffffffu, f2, o);
            }
            if (lane == 0) {
                float disc = fmaxf(fmaf(-c, f2 - 1.0f, f1 * f1), 0.0f);
                const float delta = (f1 - sqrtf(disc)) / c;
                const float tn = fminf(tau + delta, sbc[2]);
                const float dd = tn - tau;
                const float Zr = fmaf(c, dd * dd, fmaf(-2.0f * f1, dd, f2));
                sbc[0] = tn;
                sbc[1] = -__logf(fmaxf(Zr, 1.0e-30f));
            }
        }
        __syncthreads();
        tau = sbc[0];
        nlZ = sbc[1];
    }

    // ---- Pass 2: re-read row (L2-hot, last-use) and stream output ------
    #pragma unroll 4
    for (int j = 0; j < NITER; j++) {
        const int i4 = tid + j * NT;
        if (i4 < NVROW) {
            const float4 v = __ldcs(&Xr[i4]);     // evict-first: last use
            float4 o;
            o.x = fmaf(TWO_LN2, __log2f(fmaxf(fmaf(v.x, 0.5f, -tau), 0.0f)), nlZ);
            o.y = fmaf(TWO_LN2, __log2f(fmaxf(fmaf(v.y, 0.5f, -tau), 0.0f)), nlZ);
            o.z = fmaf(TWO_LN2, __log2f(fmaxf(fmaf(v.z, 0.5f, -tau), 0.0f)), nlZ);
            o.w = fmaf(TWO_LN2, __log2f(fmaxf(fmaf(v.w, 0.5f, -tau), 0.0f)), nlZ);
            __stcs(&Yr[i4], o);                   // streaming store
        }
    }
}

extern "C" void kernel_launch(void* const* d_in, const int* in_sizes, int n_in,
                              void* d_out, int out_size)
{
    const float* X = (const float*)d_in[0];
    float*       Y = (float*)d_out;
    const int rows = in_sizes[0] / D_DIM;     // 4096
    log_entmax_kernel<<<rows, NT>>>(X, Y);
}

// round 10
// speedup vs baseline: 1.4023x; 1.0399x over previous
// LogEntmaxBisect — log(entmax_1.5(X)) for X[4096, 32000] fp32.
//
// R10 = R9 + 48KB smem staging of each row's head. Pass 1 streams the row:
// first 3008 float4 (48KB) via __ldcs + STS into smem (never re-read from
// L2), rest via 256-bit L2::evict_last loads (pinned for pass-2 reuse).
// Pass 2 serves the staged 38% from LDS and the rest via __ldcs; output via
// __stcs. Cuts LTS traffic ~25% (suspected binding resource at 78% DRAM)
// and shrinks the pinned L2 set 76->47MB. fp64-accum / fp32-sqrt+log solve.

#include <cuda_runtime.h>
#include <math.h>

#define D_DIM   32000
#define NT      384
#define NVROW   (D_DIM / 4)       // 8000 float4 per row
#define NROW8   (D_DIM / 8)       // 4000 float8 per row
#define SH4     3008              // staged float4 count (48128 B)
#define SH8     (SH4 / 2)         // 1504 (float8 boundary)
#define NITER_A 8                 // ceil(3008 / 384)
#define NITER_B 7                 // ceil((4000-1504) / 384)
#define NITER_C 13                // (8000-3008) / 384 = 13 exactly
#define NWARP   (NT / 32)         // 12
#define TAU_GAP 0.005590169943749474   // (1/d)^(alpha-1) = 1/sqrt(32000)
#define TWO_LN2 1.3862943611198906f

// 256-bit load with L2 evict_last (keep for this CTA's pass-2 reuse)
__device__ __forceinline__ void ldg256_keep(const float* p, float* v)
{
    unsigned r0, r1, r2, r3, r4, r5, r6, r7;
    asm("ld.global.L2::evict_last.v8.b32 {%0,%1,%2,%3,%4,%5,%6,%7}, [%8];"
        : "=r"(r0), "=r"(r1), "=r"(r2), "=r"(r3),
          "=r"(r4), "=r"(r5), "=r"(r6), "=r"(r7) : "l"(p));
    v[0] = __uint_as_float(r0); v[1] = __uint_as_float(r1);
    v[2] = __uint_as_float(r2); v[3] = __uint_as_float(r3);
    v[4] = __uint_as_float(r4); v[5] = __uint_as_float(r5);
    v[6] = __uint_as_float(r6); v[7] = __uint_as_float(r7);
}

__global__ void __launch_bounds__(NT, 4)
log_entmax_kernel(const float* __restrict__ X, float* __restrict__ Y)
{
    const int tid  = threadIdx.x;
    const int lane = tid & 31;
    const int wid  = tid >> 5;          // 0..11

    __shared__ float4 stage[SH4];       // 48128 B row head
    __shared__ float  sred[4 * NWARP];
    __shared__ float  sbc[3];           // [0]=tau [1]=-log(Z) or sentinel [2]=tau_hi

    const size_t base = (size_t)blockIdx.x * D_DIM;
    const float*  __restrict__ Xs = X + base;
    const float4* __restrict__ Xr = (const float4*)Xs;
    float4*       __restrict__ Yr = (float4*)(Y + base);

    // ---- Pass 1a: staged head — __ldcs + STS, accumulate stats ---------
    float M = -3.0e38f, mn = 3.0e38f, S1 = 0.0f, S2 = 0.0f;
    #pragma unroll
    for (int j = 0; j < NITER_A; j++) {
        const int i4 = tid + j * NT;
        if (i4 < SH4) {
            const float4 v = __ldcs(&Xr[i4]);   // to smem; no L2 reuse
            stage[i4] = v;
            M  = fmaxf(M,  fmaxf(fmaxf(v.x, v.y), fmaxf(v.z, v.w)));
            mn = fminf(mn, fminf(fminf(v.x, v.y), fminf(v.z, v.w)));
            S1 += ((v.x + v.y) + (v.z + v.w));
            S2 = fmaf(v.x, v.x, S2); S2 = fmaf(v.y, v.y, S2);
            S2 = fmaf(v.z, v.z, S2); S2 = fmaf(v.w, v.w, S2);
        }
    }
    // ---- Pass 1b: tail — 256-bit evict_last loads ----------------------
    #pragma unroll
    for (int j = 0; j < NITER_B; j++) {
        const int i8 = SH8 + tid + j * NT;
        if (i8 < NROW8) {
            float v[8];
            ldg256_keep(Xs + i8 * 8, v);
            #pragma unroll
            for (int q = 0; q < 8; q++) {
                M  = fmaxf(M,  v[q]);
                mn = fminf(mn, v[q]);
                S1 += v[q];
                S2 = fmaf(v[q], v[q], S2);
            }
        }
    }

    // ---- Single block reduction of 4 values ----------------------------
    #pragma unroll
    for (int o = 16; o > 0; o >>= 1) {
        M  = fmaxf(M,  __shfl_xor_sync(0xffffffffu, M,  o));
        mn = fminf(mn, __shfl_xor_sync(0xffffffffu, mn, o));
        S1 += __shfl_xor_sync(0xffffffffu, S1, o);
        S2 += __shfl_xor_sync(0xffffffffu, S2, o);
    }
    if (lane == 0) {
        sred[wid] = M; sred[NWARP + wid] = mn;
        sred[2 * NWARP + wid] = S1; sred[3 * NWARP + wid] = S2;
    }
    __syncthreads();
    if (wid == 0) {
        float m = (lane < NWARP) ? sred[lane]             : -3.0e38f;
        float n = (lane < NWARP) ? sred[NWARP + lane]     :  3.0e38f;
        float a = (lane < NWARP) ? sred[2 * NWARP + lane] :  0.0f;
        float b = (lane < NWARP) ? sred[3 * NWARP + lane] :  0.0f;
        #pragma unroll
        for (int o = 8; o > 0; o >>= 1) {
            m = fmaxf(m, __shfl_xor_sync(0xffffffffu, m, o));
            n = fminf(n, __shfl_xor_sync(0xffffffffu, n, o));
            a += __shfl_xor_sync(0xffffffffu, a, o);
            b += __shfl_xor_sync(0xffffffffu, b, o);
        }
        if (lane == 0) {
            // Scalar solve: fp64 accumulation, fp32 sqrt/log
            const double d   = (double)D_DIM;
            const double mu  = 0.5 * (double)a / d;
            const double S2q = 0.25 * (double)b;
            const double V   = S2q - d * mu * mu;        // Sum (Xs - mu)^2
            const double m2  = 0.5 * (double)m;
            const double thi = m2 - TAU_GAP;             // tau_hi
            const double arg = (1.0 - V) / d;
            double t = (arg > 0.0) ? (mu - (double)sqrtf((float)arg)) : (m2 - 1.0);
            if (t > thi)      t = thi;
            if (t < m2 - 1.0) t = m2 - 1.0;
            const float tauf = (float)t;
            const bool dense = (arg > 0.0) && (0.5 * (double)n > (double)tauf);
            const double dmu = mu - (double)tauf;
            const double Z   = V + d * dmu * dmu;        // ~1 by construction
            sbc[0] = tauf;
            sbc[1] = dense ? (-__logf((float)Z)) : 1.0e30f;  // sentinel -> refine
            sbc[2] = (float)thi;
        }
    }
    __syncthreads();
    float tau = sbc[0];
    float nlZ = sbc[1];

    // ---- Fallback: one generic active-set quadratic refinement ---------
    // (plain re-read; never taken on dense-support data)
    if (nlZ > 1.0e29f) {                   // uniform across block
        __syncthreads();
        float C = 0.0f, F1 = 0.0f, F2 = 0.0f;
        #pragma unroll 4
        for (int j = 0; j < 21; j++) {
            const int i4 = tid + j * NT;
            if (i4 < NVROW) {
                const float4 v = Xr[i4];
                #pragma unroll
                for (int q = 0; q < 4; q++) {
                    const float xv = (q == 0) ? v.x : (q == 1) ? v.y : (q == 2) ? v.z : v.w;
                    const float t = fmaf(xv, 0.5f, -tau);
                    const float rr = fmaxf(t, 0.0f);
                    if (t > 0.0f) C += 1.0f;
                    F1 += rr;
                    F2 = fmaf(rr, rr, F2);
                }
            }
        }
        #pragma unroll
        for (int o = 16; o > 0; o >>= 1) {
            C  += __shfl_xor_sync(0xffffffffu, C,  o);
            F1 += __shfl_xor_sync(0xffffffffu, F1, o);
            F2 += __shfl_xor_sync(0xffffffffu, F2, o);
        }
        if (lane == 0) { sred[wid] = C; sred[NWARP + wid] = F1; sred[2 * NWARP + wid] = F2; }
        __syncthreads();
        if (wid == 0) {
            float c  = (lane < NWARP) ? sred[lane]             : 0.0f;
            float f1 = (lane < NWARP) ? sred[NWARP + lane]     : 0.0f;
            float f2 = (lane < NWARP) ? sred[2 * NWARP + lane] : 0.0f;
            #pragma unroll
            for (int o = 8; o > 0; o >>= 1) {
                c  += __shfl_xor_sync(0xffffffffu, c,  o);
                f1 += __shfl_xor_sync(0xffffffffu, f1, o);
                f2 += __shfl_xor_sync(0xffffffffu, f2, o);
            }
            if (lane == 0) {
                float disc = fmaxf(fmaf(-c, f2 - 1.0f, f1 * f1), 0.0f);
                const float delta = (f1 - sqrtf(disc)) / c;
                const float tn = fminf(tau + delta, sbc[2]);
                const float dd = tn - tau;
                const float Zr = fmaf(c, dd * dd, fmaf(-2.0f * f1, dd, f2));
                sbc[0] = tn;
                sbc[1] = -__logf(fmaxf(Zr, 1.0e-30f));
            }
        }
        __syncthreads();
        tau = sbc[0];
        nlZ = sbc[1];
    }

    // ---- Pass 2a: staged head from smem, stream output -----------------
    #pragma unroll 4
    for (int j = 0; j < NITER_A; j++) {
        const int i4 = tid + j * NT;
        if (i4 < SH4) {
            const float4 v = stage[i4];
            float4 o;
            o.x = fmaf(TWO_LN2, __log2f(fmaxf(fmaf(v.x, 0.5f, -tau), 0.0f)), nlZ);
            o.y = fmaf(TWO_LN2, __log2f(fmaxf(fmaf(v.y, 0.5f, -tau), 0.0f)), nlZ);
            o.z = fmaf(TWO_LN2, __log2f(fmaxf(fmaf(v.z, 0.5f, -tau), 0.0f)), nlZ);
            o.w = fmaf(TWO_LN2, __log2f(fmaxf(fmaf(v.w, 0.5f, -tau), 0.0f)), nlZ);
            __stcs(&Yr[i4], o);
        }
    }
    // ---- Pass 2b: tail re-read (L2-hot, last-use), stream output -------
    #pragma unroll 4
    for (int j = 0; j < NITER_C; j++) {
        const int i4 = SH4 + tid + j * NT;   // exact: 4992 = 13*384
        const float4 v = __ldcs(&Xr[i4]);
        float4 o;
        o.x = fmaf(TWO_LN2, __log2f(fmaxf(fmaf(v.x, 0.5f, -tau), 0.0f)), nlZ);
        o.y = fmaf(TWO_LN2, __log2f(fmaxf(fmaf(v.y, 0.5f, -tau), 0.0f)), nlZ);
        o.z = fmaf(TWO_LN2, __log2f(fmaxf(fmaf(v.z, 0.5f, -tau), 0.0f)), nlZ);
        o.w = fmaf(TWO_LN2, __log2f(fmaxf(fmaf(v.w, 0.5f, -tau), 0.0f)), nlZ);
        __stcs(&Yr[i4], o);
    }
}

extern "C" void kernel_launch(void* const* d_in, const int* in_sizes, int n_in,
                              void* d_out, int out_size)
{
    const float* X = (const float*)d_in[0];
    float*       Y = (float*)d_out;
    const int rows = in_sizes[0] / D_DIM;     // 4096
    log_entmax_kernel<<<rows, NT>>>(X, Y);
}